// round 2
// baseline (speedup 1.0000x reference)
#include <cuda_runtime.h>
#include <cuda_bf16.h>
#include <cstdint>

// Problem dims
#define BB   512
#define NN   512
#define MTOT (BB*NN)      // 262144 rows
#define C1   128
#define C2   256
#define ENC  128
#define EPSV 1e-5f

// mask is passed by the harness as a 4-byte type (int32 or float32 widened
// from JAX bool). Nonzero bit pattern <=> true for both encodings.
#define MASK_AT(mk, i) ((mk)[i] != 0)

// ---------------- scratch (static __device__, no allocations) ----------------
__device__ float g_h1[(size_t)MTOT * C1];   // h1 pre-BN  [BN,128]; reused as h2out [BN,128]
__device__ float g_h [(size_t)MTOT * C2];   // masked h   [BN,256]
__device__ float g_h2[(size_t)MTOT * C2];   // h2 pre-BN  [BN,256]
__device__ float g_pool [BB * C2];          // [B,256]
__device__ float g_pbias[BB * C2];          // [B,256]  pooled@W3b + b3
__device__ float g_stat[768];               // [0:128) sum1, [128:256) sumsq1, [256:512) sum2, [512:768) sumsq2
__device__ float g_cnt;
__device__ float g_scale1[C1], g_shift1[C1];
__device__ float g_scale2[C2], g_shift2[C2];

// ---------------- zero stats ----------------
__global__ void zero_stats_kernel() {
    int t = threadIdx.x;
    for (int i = t; i < 768; i += blockDim.x) g_stat[i] = 0.f;
    if (t == 0) g_cnt = 0.f;
}

// ---------------- K1: h1 = x@W1 + b1, accumulate masked BN1 stats ----------------
// 128 threads (1 per channel), 32 rows per block
__global__ __launch_bounds__(128) void k1_kernel(const float* __restrict__ x,
                                                 const int* __restrict__ mask,
                                                 const float* __restrict__ W1,
                                                 const float* __restrict__ b1) {
    __shared__ float sW[6 * C1];
    __shared__ float sb[C1];
    int c = threadIdx.x;
#pragma unroll
    for (int k = 0; k < 6; k++) sW[k * C1 + c] = W1[k * C1 + c];
    sb[c] = b1[c];
    __syncthreads();

    int row0 = blockIdx.x * 32;
    float s = 0.f, ss = 0.f;
    int cnt = 0;
    for (int r = 0; r < 32; r++) {
        int row = row0 + r;
        const float* xr = x + (size_t)row * 6;
        float v = sb[c];
#pragma unroll
        for (int k = 0; k < 6; k++) v = fmaf(xr[k], sW[k * C1 + c], v);
        g_h1[(size_t)row * C1 + c] = v;
        if (MASK_AT(mask, row)) { s += v; ss += v * v; cnt++; }
    }
    atomicAdd(&g_stat[c],        s);
    atomicAdd(&g_stat[C1 + c],   ss);
    if (c == 0) atomicAdd(&g_cnt, (float)cnt);
}

// ---------------- finalize BN params ----------------
__global__ void fin1_kernel(const float* __restrict__ g1, const float* __restrict__ be1) {
    int c = threadIdx.x;  // 128
    float cnt  = fmaxf(g_cnt, 1.f);
    float mean = g_stat[c] / cnt;
    float var  = g_stat[C1 + c] / cnt - mean * mean;
    float sc   = g1[c] * rsqrtf(var + EPSV);
    g_scale1[c] = sc;
    g_shift1[c] = be1[c] - mean * sc;
}

__global__ void fin2_kernel(const float* __restrict__ g2, const float* __restrict__ be2) {
    int c = threadIdx.x;  // 256
    float cnt  = fmaxf(g_cnt, 1.f);
    float mean = g_stat[256 + c] / cnt;
    float var  = g_stat[512 + c] / cnt - mean * mean;
    float sc   = g2[c] * rsqrtf(var + EPSV);
    g_scale2[c] = sc;
    g_shift2[c] = be2[c] - mean * sc;
}

// ---------------- tiled SGEMM 128x128x16, 256 thr, 8x8 micro-tile ----------------
// MODE 2: g_h  = relu(bn1(g_h1)) @ W2 + b2, * mask        (K=128, N=256)
// MODE 3: g_h2 = g_h @ W3[0:256] + g_pbias[batch]          (K=256, N=256)
// MODE 4: g_h1 = relu(bn2(g_h2)) @ W4 + b4, * mask        (K=256, N=128)
template <int MODE>
__global__ __launch_bounds__(256) void gemm_kernel(const float* __restrict__ Bm,
                                                   const float* __restrict__ biasv,
                                                   const int* __restrict__ mask) {
    constexpr int KDIM    = (MODE == 2) ? 128 : 256;
    constexpr int NDIM    = (MODE == 4) ? 128 : 256;
    constexpr bool BNACT  = (MODE != 3);
    constexpr bool MASKM  = (MODE != 3);
    constexpr bool ROWB   = (MODE == 3);
    constexpr int BK = 16, PAD = 132;

    const float* A     = (MODE == 2) ? g_h1 : (MODE == 3) ? g_h : g_h2;
    float*       Out   = (MODE == 2) ? g_h  : (MODE == 3) ? g_h2 : g_h1;
    const float* scale = (MODE == 2) ? g_scale1 : g_scale2;
    const float* shift = (MODE == 2) ? g_shift1 : g_shift2;

    __shared__ __align__(16) float As[BK * PAD];
    __shared__ __align__(16) float Bs[BK * PAD];

    int t = threadIdx.x;
    int rowBase = blockIdx.x * 128;
    int nBase   = blockIdx.y * 128;

    int txa = t & 15, tya = t >> 4;     // A tile load: txa = k, tya = row base
    int txb = t & 127, tyb = t >> 7;    // B tile load: txb = n, tyb = k base
    int tm = t >> 4, tn = t & 15;       // micro-tile coords

    float acc[8][8];
#pragma unroll
    for (int i = 0; i < 8; i++)
#pragma unroll
        for (int j = 0; j < 8; j++) acc[i][j] = 0.f;

    for (int kb = 0; kb < KDIM; kb += BK) {
        float sc, sh;
        if (BNACT) { sc = scale[kb + txa]; sh = shift[kb + txa]; }
#pragma unroll
        for (int i = 0; i < 8; i++) {
            int m = tya + i * 16;
            float v = A[(size_t)(rowBase + m) * KDIM + kb + txa];
            if (BNACT) v = fmaxf(fmaf(v, sc, sh), 0.f);
            As[txa * PAD + m] = v;
        }
#pragma unroll
        for (int j = 0; j < 8; j++) {
            int k = tyb + j * 2;
            Bs[k * PAD + txb] = Bm[(size_t)(kb + k) * NDIM + nBase + txb];
        }
        __syncthreads();
#pragma unroll
        for (int k = 0; k < BK; k++) {
            float a[8], b[8];
            *(float4*)&a[0] = *(const float4*)&As[k * PAD + tm * 8];
            *(float4*)&a[4] = *(const float4*)&As[k * PAD + tm * 8 + 4];
            *(float4*)&b[0] = *(const float4*)&Bs[k * PAD + tn * 8];
            *(float4*)&b[4] = *(const float4*)&Bs[k * PAD + tn * 8 + 4];
#pragma unroll
            for (int i = 0; i < 8; i++)
#pragma unroll
                for (int j = 0; j < 8; j++) acc[i][j] = fmaf(a[i], b[j], acc[i][j]);
        }
        __syncthreads();
    }

    // epilogue
#pragma unroll
    for (int i = 0; i < 8; i++) {
        int row = rowBase + tm * 8 + i;
        float mval = 1.f;
        if (MASKM) mval = MASK_AT(mask, row) ? 1.f : 0.f;
        int bidx = row >> 9;  // row / NN
        float* op = Out + (size_t)row * NDIM + nBase + tn * 8;
#pragma unroll
        for (int j4 = 0; j4 < 8; j4 += 4) {
            float4 v;
            float tmp[4];
#pragma unroll
            for (int q = 0; q < 4; q++) {
                int col = nBase + tn * 8 + j4 + q;
                float vv = acc[i][j4 + q];
                if (biasv) vv += biasv[col];
                if (ROWB)  vv += g_pbias[bidx * NDIM + col];
                tmp[q] = vv * mval;
            }
            v.x = tmp[0]; v.y = tmp[1]; v.z = tmp[2]; v.w = tmp[3];
            *(float4*)(op + j4) = v;
        }
    }
}

// ---------------- pooled max over N (zeros at invalid rows participate) ----------------
__global__ void poolmax_kernel() {
    int b = blockIdx.x, c = threadIdx.x;  // 256 threads
    float mx = -3.4e38f;
    const float* p = g_h + ((size_t)b * NN) * C2 + c;
    for (int n = 0; n < NN; n++) mx = fmaxf(mx, p[(size_t)n * C2]);
    g_pool[b * C2 + c] = mx;
}

// ---------------- pbias = pooled @ W3[256:512] + b3 ----------------
__global__ void pbias_kernel(const float* __restrict__ W3, const float* __restrict__ b3) {
    __shared__ float sp[C2];
    int b = blockIdx.x, c = threadIdx.x;  // 256 threads
    sp[c] = g_pool[b * C2 + c];
    __syncthreads();
    float v = b3[c];
    for (int k = 0; k < C2; k++) v = fmaf(sp[k], W3[(size_t)(C2 + k) * C2 + c], v);
    g_pbias[b * C2 + c] = v;
}

// ---------------- masked BN2 stats over g_h2 ----------------
__global__ __launch_bounds__(256) void stats2_kernel(const int* __restrict__ mask) {
    int c = threadIdx.x;
    int row0 = blockIdx.x * 32;
    float s = 0.f, ss = 0.f;
    for (int r = 0; r < 32; r++) {
        int row = row0 + r;
        if (MASK_AT(mask, row)) {
            float v = g_h2[(size_t)row * C2 + c];
            s += v; ss += v * v;
        }
    }
    atomicAdd(&g_stat[256 + c], s);
    atomicAdd(&g_stat[512 + c], ss);
}

// ---------------- final max over N -> out [B,ENC] ----------------
__global__ void finalmax_kernel(float* __restrict__ out) {
    int b = blockIdx.x, c = threadIdx.x;  // 128 threads
    float mx = -3.4e38f;
    const float* p = g_h1 + ((size_t)b * NN) * ENC + c;
    for (int n = 0; n < NN; n++) mx = fmaxf(mx, p[(size_t)n * ENC]);
    out[b * ENC + c] = mx;
}

// ---------------- launch ----------------
extern "C" void kernel_launch(void* const* d_in, const int* in_sizes, int n_in,
                              void* d_out, int out_size) {
    const float* x       = (const float*)d_in[0];
    const int*   mk      = (const int*)d_in[1];
    const float* W1 = (const float*)d_in[2];
    const float* b1 = (const float*)d_in[3];
    const float* g1 = (const float*)d_in[4];
    const float* be1= (const float*)d_in[5];
    const float* W2 = (const float*)d_in[6];
    const float* b2 = (const float*)d_in[7];
    const float* W3 = (const float*)d_in[8];
    const float* b3 = (const float*)d_in[9];
    const float* g2 = (const float*)d_in[10];
    const float* be2= (const float*)d_in[11];
    const float* W4 = (const float*)d_in[12];
    const float* b4 = (const float*)d_in[13];
    float* out = (float*)d_out;

    zero_stats_kernel<<<1, 256>>>();
    k1_kernel<<<MTOT / 32, 128>>>(x, mk, W1, b1);
    fin1_kernel<<<1, 128>>>(g1, be1);
    gemm_kernel<2><<<dim3(MTOT / 128, 2), 256>>>(W2, b2, mk);
    poolmax_kernel<<<BB, 256>>>();
    pbias_kernel<<<BB, 256>>>(W3, b3);
    gemm_kernel<3><<<dim3(MTOT / 128, 2), 256>>>(W3, nullptr, nullptr);
    stats2_kernel<<<MTOT / 32, 256>>>(mk);
    fin2_kernel<<<1, 256>>>(g2, be2);
    gemm_kernel<4><<<dim3(MTOT / 128, 1), 256>>>(W4, b4, mk);
    finalmax_kernel<<<BB, 128>>>(out);
}

// round 4
// speedup vs baseline: 1.7271x; 1.7271x over previous
#include <cuda_runtime.h>
#include <cstdint>

// Problem dims
#define BB   512
#define NN   512
#define MTOT (BB*NN)      // 262144 rows
#define C1   128
#define C2   256
#define ENC  128
#define EPSV 1e-5f

#define MASK_AT(mk, i) ((mk)[i] != 0)

// ---------------- scratch ----------------
__device__ float g_h1[(size_t)MTOT * C1];   // h1 pre-BN [BN,128]; reused as final h2out [BN,128]
__device__ float g_h [(size_t)MTOT * C2];   // masked h  [BN,256]
__device__ float g_h2[(size_t)MTOT * C2];   // h2 pre-BN [BN,256]
__device__ float g_pool [BB * C2];
__device__ float g_pbias[BB * C2];
__device__ float g_stat[768];
__device__ float g_cnt;
__device__ float g_scale1[C1], g_shift1[C1];
__device__ float g_scale2[C2], g_shift2[C2];

__device__ __forceinline__ float to_tf32(float v) {
    asm("cvt.rna.tf32.f32 %0, %1;" : "=f"(v) : "f"(v));
    return v;
}

// ---------------- zero stats ----------------
__global__ void zero_stats_kernel() {
    int t = threadIdx.x;
    for (int i = t; i < 768; i += blockDim.x) g_stat[i] = 0.f;
    if (t == 0) g_cnt = 0.f;
}

// ---------------- K1: h1 = x@W1 + b1, masked BN1 stats ----------------
__global__ __launch_bounds__(128) void k1_kernel(const float* __restrict__ x,
                                                 const int* __restrict__ mask,
                                                 const float* __restrict__ W1,
                                                 const float* __restrict__ b1) {
    __shared__ float sW[6 * C1];
    __shared__ float sb[C1];
    int c = threadIdx.x;
#pragma unroll
    for (int k = 0; k < 6; k++) sW[k * C1 + c] = W1[k * C1 + c];
    sb[c] = b1[c];
    __syncthreads();

    int row0 = blockIdx.x * 32;
    float s = 0.f, ss = 0.f;
    int cnt = 0;
    for (int r = 0; r < 32; r++) {
        int row = row0 + r;
        const float* xr = x + (size_t)row * 6;
        float v = sb[c];
#pragma unroll
        for (int k = 0; k < 6; k++) v = fmaf(xr[k], sW[k * C1 + c], v);
        g_h1[(size_t)row * C1 + c] = v;
        if (MASK_AT(mask, row)) { s += v; ss += v * v; cnt++; }
    }
    atomicAdd(&g_stat[c],      s);
    atomicAdd(&g_stat[C1 + c], ss);
    if (c == 0) atomicAdd(&g_cnt, (float)cnt);
}

// ---------------- finalize BN ----------------
__global__ void fin1_kernel(const float* __restrict__ g1, const float* __restrict__ be1) {
    int c = threadIdx.x;
    float cnt  = fmaxf(g_cnt, 1.f);
    float mean = g_stat[c] / cnt;
    float var  = g_stat[C1 + c] / cnt - mean * mean;
    float sc   = g1[c] * rsqrtf(var + EPSV);
    g_scale1[c] = sc;
    g_shift1[c] = be1[c] - mean * sc;
}
__global__ void fin2_kernel(const float* __restrict__ g2, const float* __restrict__ be2) {
    int c = threadIdx.x;
    float cnt  = fmaxf(g_cnt, 1.f);
    float mean = g_stat[256 + c] / cnt;
    float var  = g_stat[512 + c] / cnt - mean * mean;
    float sc   = g2[c] * rsqrtf(var + EPSV);
    g_scale2[c] = sc;
    g_shift2[c] = be2[c] - mean * sc;
}

// ================ tf32 mma.sync GEMM ================
// Out[M,N] = f(A[M,K]) @ W[K,N] + bias.  CTA tile 128x128, 8 warps (4m x 2n),
// warp tile 32x64, BK=16, mma m16n8k8 tf32.
// MODE 2: A=g_h1 (K=128), f=BN1+ReLU, bias=b2,   mask -> g_h   (N=256)
// MODE 3: A=g_h  (K=256), f=id,       bias=pbias, -   -> g_h2  (N=256)
// MODE 4: A=g_h2 (K=256), f=BN2+ReLU, bias=b4,   mask -> g_h1  (N=128)
#define PADA 20
#define PADN 136

template <int KDIM, int NDIM, int MODE>
__global__ __launch_bounds__(256) void mma_gemm(const float* __restrict__ Wg,
                                                const float* __restrict__ biasv,
                                                const int* __restrict__ mask) {
    constexpr bool BNACT = (MODE != 3);
    constexpr bool MASKM = (MODE != 3);

    const float* A   = (MODE == 2) ? g_h1 : (MODE == 3) ? g_h : g_h2;
    float*       Out = (MODE == 2) ? g_h  : (MODE == 3) ? g_h2 : g_h1;

    __shared__ __align__(16) float As[128 * PADA];   // [m][k] row-major, PADA stride
    __shared__ __align__(16) float Bs[16 * PADN];    // [k][n]
    __shared__ float sBias[128];
    __shared__ float sScale[KDIM > 0 ? KDIM : 1];
    __shared__ float sShift[KDIM > 0 ? KDIM : 1];

    const int t = threadIdx.x;
    const int rowBase = blockIdx.x * 128;
    const int nBase   = blockIdx.y * 128;
    const int batch   = rowBase >> 9;

    if (MODE == 3) {
        if (t < 128) sBias[t] = g_pbias[batch * C2 + nBase + t];
    } else {
        if (t < 128) sBias[t] = biasv[nBase + t];
        const float* sc = (MODE == 2) ? g_scale1 : g_scale2;
        const float* sh = (MODE == 2) ? g_shift1 : g_shift2;
        for (int r = t; r < KDIM; r += 256) { sScale[r] = sc[r]; sShift[r] = sh[r]; }
    }

    // warp / lane decomposition
    const int w  = t >> 5, l = t & 31;
    const int g  = l >> 2, c = l & 3;
    const int wm = w & 3, wn = w >> 2;           // 4 m-warps x 2 n-warps
    const int mrow0 = wm * 32;                   // warp row offset in tile
    const int ncol0 = wn * 64;                   // warp col offset in tile

    // global A load mapping: thread -> row t>>1, k-half (t&1)*8
    const int arow = t >> 1, ak0 = (t & 1) * 8;
    const float* aptr = A + (size_t)(rowBase + arow) * KDIM + ak0;
    // global B load mapping: thread -> k t>>4, n (t&15)*8
    const int bk = t >> 4, bn0 = (t & 15) * 8;
    const float* bptr = Wg + (size_t)bk * NDIM + nBase + bn0;

    float acc[2][8][4];
#pragma unroll
    for (int mt = 0; mt < 2; mt++)
#pragma unroll
        for (int nt = 0; nt < 8; nt++)
#pragma unroll
            for (int q = 0; q < 4; q++) acc[mt][nt][q] = 0.f;

    __syncthreads();

#pragma unroll 1
    for (int kb = 0; kb < KDIM / 16; kb++) {
        // ---- A tile: 128x16, BN+ReLU+tf32 on load ----
        {
            float4 v0 = *(const float4*)(aptr + kb * 16);
            float4 v1 = *(const float4*)(aptr + kb * 16 + 4);
            if (BNACT) {
                int k0 = kb * 16 + ak0;
                v0.x = fmaxf(fmaf(v0.x, sScale[k0+0], sShift[k0+0]), 0.f);
                v0.y = fmaxf(fmaf(v0.y, sScale[k0+1], sShift[k0+1]), 0.f);
                v0.z = fmaxf(fmaf(v0.z, sScale[k0+2], sShift[k0+2]), 0.f);
                v0.w = fmaxf(fmaf(v0.w, sScale[k0+3], sShift[k0+3]), 0.f);
                v1.x = fmaxf(fmaf(v1.x, sScale[k0+4], sShift[k0+4]), 0.f);
                v1.y = fmaxf(fmaf(v1.y, sScale[k0+5], sShift[k0+5]), 0.f);
                v1.z = fmaxf(fmaf(v1.z, sScale[k0+6], sShift[k0+6]), 0.f);
                v1.w = fmaxf(fmaf(v1.w, sScale[k0+7], sShift[k0+7]), 0.f);
            }
            v0.x = to_tf32(v0.x); v0.y = to_tf32(v0.y); v0.z = to_tf32(v0.z); v0.w = to_tf32(v0.w);
            v1.x = to_tf32(v1.x); v1.y = to_tf32(v1.y); v1.z = to_tf32(v1.z); v1.w = to_tf32(v1.w);
            *(float4*)&As[arow * PADA + ak0]     = v0;
            *(float4*)&As[arow * PADA + ak0 + 4] = v1;
        }
        // ---- B tile: 16x128 ----
        {
            float4 v0 = *(const float4*)(bptr + (size_t)kb * 16 * NDIM);
            float4 v1 = *(const float4*)(bptr + (size_t)kb * 16 * NDIM + 4);
            v0.x = to_tf32(v0.x); v0.y = to_tf32(v0.y); v0.z = to_tf32(v0.z); v0.w = to_tf32(v0.w);
            v1.x = to_tf32(v1.x); v1.y = to_tf32(v1.y); v1.z = to_tf32(v1.z); v1.w = to_tf32(v1.w);
            *(float4*)&Bs[bk * PADN + bn0]     = v0;
            *(float4*)&Bs[bk * PADN + bn0 + 4] = v1;
        }
        __syncthreads();

#pragma unroll
        for (int ks = 0; ks < 2; ks++) {
            const int kk = ks * 8;
            float a[2][4];
#pragma unroll
            for (int mt = 0; mt < 2; mt++) {
                const float* ap = &As[(mrow0 + mt * 16 + g) * PADA + kk];
                a[mt][0] = ap[c];
                a[mt][2] = ap[c + 4];
                const float* ap8 = ap + 8 * PADA;
                a[mt][1] = ap8[c];
                a[mt][3] = ap8[c + 4];
            }
#pragma unroll
            for (int nt = 0; nt < 8; nt++) {
                float b0 = Bs[(kk + c) * PADN + ncol0 + nt * 8 + g];
                float b1 = Bs[(kk + c + 4) * PADN + ncol0 + nt * 8 + g];
#pragma unroll
                for (int mt = 0; mt < 2; mt++) {
                    asm volatile(
                        "mma.sync.aligned.m16n8k8.row.col.f32.tf32.tf32.f32 "
                        "{%0,%1,%2,%3}, {%4,%5,%6,%7}, {%8,%9}, {%0,%1,%2,%3};"
                        : "+f"(acc[mt][nt][0]), "+f"(acc[mt][nt][1]),
                          "+f"(acc[mt][nt][2]), "+f"(acc[mt][nt][3])
                        : "r"(__float_as_uint(a[mt][0])), "r"(__float_as_uint(a[mt][1])),
                          "r"(__float_as_uint(a[mt][2])), "r"(__float_as_uint(a[mt][3])),
                          "r"(__float_as_uint(b0)), "r"(__float_as_uint(b1)));
                }
            }
        }
        __syncthreads();
    }

    // ---- epilogue ----
#pragma unroll
    for (int mt = 0; mt < 2; mt++) {
        int r0 = rowBase + mrow0 + mt * 16 + g;
        int r1 = r0 + 8;
        float m0 = 1.f, m1 = 1.f;
        if (MASKM) {
            m0 = MASK_AT(mask, r0) ? 1.f : 0.f;
            m1 = MASK_AT(mask, r1) ? 1.f : 0.f;
        }
        float* o0 = Out + (size_t)r0 * NDIM + nBase;
        float* o1 = Out + (size_t)r1 * NDIM + nBase;
#pragma unroll
        for (int nt = 0; nt < 8; nt++) {
            int col = ncol0 + nt * 8 + 2 * c;
            float bx = sBias[col], by = sBias[col + 1];
            float2 u, v;
            u.x = (acc[mt][nt][0] + bx) * m0;
            u.y = (acc[mt][nt][1] + by) * m0;
            v.x = (acc[mt][nt][2] + bx) * m1;
            v.y = (acc[mt][nt][3] + by) * m1;
            *(float2*)(o0 + col) = u;
            *(float2*)(o1 + col) = v;
        }
    }
}

// ---------------- pooled max over N ----------------
__global__ void poolmax_kernel() {
    int b = blockIdx.x, c = threadIdx.x;  // 256
    float mx = -3.4e38f;
    const float* p = g_h + ((size_t)b * NN) * C2 + c;
    for (int n = 0; n < NN; n++) mx = fmaxf(mx, p[(size_t)n * C2]);
    g_pool[b * C2 + c] = mx;
}

// ---------------- pbias = pooled @ W3[256:512] + b3 ----------------
__global__ void pbias_kernel(const float* __restrict__ W3, const float* __restrict__ b3) {
    __shared__ float sp[C2];
    int b = blockIdx.x, c = threadIdx.x;  // 256
    sp[c] = g_pool[b * C2 + c];
    __syncthreads();
    float v = b3[c];
    for (int k = 0; k < C2; k++) v = fmaf(sp[k], W3[(size_t)(C2 + k) * C2 + c], v);
    g_pbias[b * C2 + c] = v;
}

// ---------------- masked BN2 stats ----------------
__global__ __launch_bounds__(256) void stats2_kernel(const int* __restrict__ mask) {
    int c = threadIdx.x;
    int row0 = blockIdx.x * 32;
    float s = 0.f, ss = 0.f;
    for (int r = 0; r < 32; r++) {
        int row = row0 + r;
        if (MASK_AT(mask, row)) {
            float v = g_h2[(size_t)row * C2 + c];
            s += v; ss += v * v;
        }
    }
    atomicAdd(&g_stat[256 + c], s);
    atomicAdd(&g_stat[512 + c], ss);
}

// ---------------- final max ----------------
__global__ void finalmax_kernel(float* __restrict__ out) {
    int b = blockIdx.x, c = threadIdx.x;  // 128
    float mx = -3.4e38f;
    const float* p = g_h1 + ((size_t)b * NN) * ENC + c;
    for (int n = 0; n < NN; n++) mx = fmaxf(mx, p[(size_t)n * ENC]);
    out[b * ENC + c] = mx;
}

// ---------------- launch ----------------
extern "C" void kernel_launch(void* const* d_in, const int* in_sizes, int n_in,
                              void* d_out, int out_size) {
    const float* x  = (const float*)d_in[0];
    const int*   mk = (const int*)d_in[1];
    const float* W1 = (const float*)d_in[2];
    const float* b1 = (const float*)d_in[3];
    const float* g1 = (const float*)d_in[4];
    const float* be1= (const float*)d_in[5];
    const float* W2 = (const float*)d_in[6];
    const float* b2 = (const float*)d_in[7];
    const float* W3 = (const float*)d_in[8];
    const float* b3 = (const float*)d_in[9];
    const float* g2 = (const float*)d_in[10];
    const float* be2= (const float*)d_in[11];
    const float* W4 = (const float*)d_in[12];
    const float* b4 = (const float*)d_in[13];
    float* out = (float*)d_out;

    zero_stats_kernel<<<1, 256>>>();
    k1_kernel<<<MTOT / 32, 128>>>(x, mk, W1, b1);
    fin1_kernel<<<1, 128>>>(g1, be1);

    mma_gemm<128, 256, 2><<<dim3(MTOT / 128, 2), 256>>>(W2, b2, mk);
    poolmax_kernel<<<BB, 256>>>();
    pbias_kernel<<<BB, 256>>>(W3, b3);
    mma_gemm<256, 256, 3><<<dim3(MTOT / 128, 2), 256>>>(W3, nullptr, mk);
    stats2_kernel<<<MTOT / 32, 256>>>(mk);
    fin2_kernel<<<1, 256>>>(g2, be2);
    mma_gemm<256, 128, 4><<<dim3(MTOT / 128, 1), 256>>>(W4, b4, mk);
    finalmax_kernel<<<BB, 128>>>(out);
}

// round 5
// speedup vs baseline: 2.1244x; 1.2300x over previous
#include <cuda_runtime.h>
#include <cstdint>

// Problem dims
#define BB   512
#define NN   512
#define MTOT (BB*NN)      // 262144 rows
#define C1   128
#define C2   256
#define ENC  128
#define EPSV 1e-5f

#define MASK_AT(mk, i) ((mk)[i] != 0)

// ---------------- scratch ----------------
__device__ float g_h1[(size_t)MTOT * C1];   // h1 pre-BN [BN,128]; reused as final h2out [BN,128]
__device__ float g_h [(size_t)MTOT * C2];   // masked h  [BN,256]
__device__ float g_h2[(size_t)MTOT * C2];   // h2 pre-BN [BN,256]
__device__ float g_pool [BB * C2];
__device__ float g_pbias[BB * C2];
__device__ float g_stat[768];
__device__ float g_cnt;
__device__ float g_scale1[C1], g_shift1[C1];
__device__ float g_scale2[C2], g_shift2[C2];

__device__ __forceinline__ float to_tf32(float v) {
    asm("cvt.rna.tf32.f32 %0, %1;" : "=f"(v) : "f"(v));
    return v;
}
__device__ __forceinline__ uint32_t smem_u32(const void* p) {
    uint32_t a;
    asm("{ .reg .u64 t; cvta.to.shared.u64 t, %1; cvt.u32.u64 %0, t; }" : "=r"(a) : "l"(p));
    return a;
}
__device__ __forceinline__ void cp_async16(uint32_t dst, const void* src) {
    asm volatile("cp.async.ca.shared.global [%0], [%1], 16;" :: "r"(dst), "l"(src));
}
#define CP_COMMIT() asm volatile("cp.async.commit_group;" ::: "memory")
#define CP_WAIT0()  asm volatile("cp.async.wait_group 0;" ::: "memory")

// ---------------- zero stats ----------------
__global__ void zero_stats_kernel() {
    int t = threadIdx.x;
    for (int i = t; i < 768; i += blockDim.x) g_stat[i] = 0.f;
    if (t == 0) g_cnt = 0.f;
}

// ---------------- K1: h1 = x@W1 + b1, masked BN1 stats ----------------
__global__ __launch_bounds__(128) void k1_kernel(const float* __restrict__ x,
                                                 const int* __restrict__ mask,
                                                 const float* __restrict__ W1,
                                                 const float* __restrict__ b1) {
    __shared__ float sW[6 * C1];
    __shared__ float sb[C1];
    int c = threadIdx.x;
#pragma unroll
    for (int k = 0; k < 6; k++) sW[k * C1 + c] = W1[k * C1 + c];
    sb[c] = b1[c];
    __syncthreads();

    int row0 = blockIdx.x * 32;
    float s = 0.f, ss = 0.f;
    int cnt = 0;
    for (int r = 0; r < 32; r++) {
        int row = row0 + r;
        const float* xr = x + (size_t)row * 6;
        float v = sb[c];
#pragma unroll
        for (int k = 0; k < 6; k++) v = fmaf(xr[k], sW[k * C1 + c], v);
        g_h1[(size_t)row * C1 + c] = v;
        if (MASK_AT(mask, row)) { s += v; ss += v * v; cnt++; }
    }
    atomicAdd(&g_stat[c],      s);
    atomicAdd(&g_stat[C1 + c], ss);
    if (c == 0) atomicAdd(&g_cnt, (float)cnt);
}

// ---------------- finalize BN ----------------
__global__ void fin1_kernel(const float* __restrict__ g1, const float* __restrict__ be1) {
    int c = threadIdx.x;
    float cnt  = fmaxf(g_cnt, 1.f);
    float mean = g_stat[c] / cnt;
    float var  = g_stat[C1 + c] / cnt - mean * mean;
    float sc   = g1[c] * rsqrtf(var + EPSV);
    g_scale1[c] = sc;
    g_shift1[c] = be1[c] - mean * sc;
}
__global__ void fin2_kernel(const float* __restrict__ g2, const float* __restrict__ be2) {
    int c = threadIdx.x;
    float cnt  = fmaxf(g_cnt, 1.f);
    float mean = g_stat[256 + c] / cnt;
    float var  = g_stat[512 + c] / cnt - mean * mean;
    float sc   = g2[c] * rsqrtf(var + EPSV);
    g_scale2[c] = sc;
    g_shift2[c] = be2[c] - mean * sc;
}

// ================ tf32 mma.sync GEMM, double-buffered cp.async ================
// CTA: 128x128 tile, 4 warps (2m x 2n), warp tile 64x64, BK=16.
// MODE 2: A=g_h1 (K=128), BN1+ReLU at frag, bias=b2,   mask -> g_h   (N=256)
// MODE 3: A=g_h  (K=256), identity,         bias=pbias,  -  -> g_h2  (N=256)
// MODE 4: A=g_h2 (K=256), BN2+ReLU at frag, bias=b4,   mask -> g_h1  (N=128)
#define PADA 20
#define PADN 136

template <int KDIM, int NDIM, int MODE>
__global__ __launch_bounds__(128, 2) void mma_gemm(const float* __restrict__ Wg,
                                                   const float* __restrict__ biasv,
                                                   const int* __restrict__ mask) {
    constexpr bool BNACT = (MODE != 3);
    constexpr bool MASKM = (MODE != 3);
    constexpr int  NKB   = KDIM / 16;

    const float* A   = (MODE == 2) ? g_h1 : (MODE == 3) ? g_h : g_h2;
    float*       Out = (MODE == 2) ? g_h  : (MODE == 3) ? g_h2 : g_h1;

    __shared__ __align__(16) float As[2][128 * PADA];   // raw A, [m][k] stride PADA
    __shared__ __align__(16) float Bs[2][16 * PADN];    // raw W, [k][n] stride PADN
    __shared__ float sBias[128];
    __shared__ float sScale[KDIM];
    __shared__ float sShift[KDIM];

    const int t = threadIdx.x;
    const int rowBase = blockIdx.x * 128;
    const int nBase   = blockIdx.y * 128;
    const int batch   = rowBase >> 9;

    if (MODE == 3) {
        if (t < 128) sBias[t] = g_pbias[batch * C2 + nBase + t];
    } else {
        if (t < 128) sBias[t] = biasv[nBase + t];
        const float* sc = (MODE == 2) ? g_scale1 : g_scale2;
        const float* sh = (MODE == 2) ? g_shift1 : g_shift2;
        for (int r = t; r < KDIM; r += 128) { sScale[r] = sc[r]; sShift[r] = sh[r]; }
    }

    // warp / lane decomposition
    const int w  = t >> 5, l = t & 31;
    const int g  = l >> 2, c = l & 3;
    const int wm = w & 1, wn = w >> 1;
    const int mrow0 = wm * 64;
    const int ncol0 = wn * 64;

    // cp.async mappings (4 x 16B per thread per tile)
    // A: f = i*128 + t ; r = f>>2 ; kc = f&3
    // B: f = i*128 + t ; k = f>>5 ; nc = f&31
    uint32_t asm_base[2], bsm_base[2];
    asm_base[0] = smem_u32(&As[0][0]); asm_base[1] = smem_u32(&As[1][0]);
    bsm_base[0] = smem_u32(&Bs[0][0]); bsm_base[1] = smem_u32(&Bs[1][0]);

    const float* aG = A + (size_t)rowBase * KDIM;
    const float* bG = Wg + nBase;

    auto issue_tile = [&](int kb, int buf) {
#pragma unroll
        for (int i = 0; i < 4; i++) {
            int f = i * 128 + t;
            int r = f >> 2, kc = f & 3;
            cp_async16(asm_base[buf] + (uint32_t)(r * PADA + kc * 4) * 4,
                       aG + (size_t)r * KDIM + kb * 16 + kc * 4);
        }
#pragma unroll
        for (int i = 0; i < 4; i++) {
            int f = i * 128 + t;
            int k = f >> 5, nc = f & 31;
            cp_async16(bsm_base[buf] + (uint32_t)(k * PADN + nc * 4) * 4,
                       bG + (size_t)(kb * 16 + k) * NDIM + nc * 4);
        }
        CP_COMMIT();
    };

    float acc[4][8][4];
#pragma unroll
    for (int mt = 0; mt < 4; mt++)
#pragma unroll
        for (int nt = 0; nt < 8; nt++)
#pragma unroll
            for (int q = 0; q < 4; q++) acc[mt][nt][q] = 0.f;

    issue_tile(0, 0);

#pragma unroll 1
    for (int kb = 0; kb < NKB; kb++) {
        const int buf = kb & 1;
        CP_WAIT0();
        __syncthreads();
        if (kb + 1 < NKB) issue_tile(kb + 1, buf ^ 1);

#pragma unroll
        for (int ks = 0; ks < 2; ks++) {
            const int kk = ks * 8;
            // per-lane BN params for this k-slice
            float sc0 = 1.f, sh0 = 0.f, sc4 = 1.f, sh4 = 0.f;
            if (BNACT) {
                sc0 = sScale[kb * 16 + kk + c];     sh0 = sShift[kb * 16 + kk + c];
                sc4 = sScale[kb * 16 + kk + c + 4]; sh4 = sShift[kb * 16 + kk + c + 4];
            }
            float a[4][4];
#pragma unroll
            for (int mt = 0; mt < 4; mt++) {
                const float* ap = &As[buf][(mrow0 + mt * 16 + g) * PADA + kk];
                a[mt][0] = ap[c];
                a[mt][1] = ap[8 * PADA + c];
                a[mt][2] = ap[c + 4];
                a[mt][3] = ap[8 * PADA + c + 4];
                if (BNACT) {
                    a[mt][0] = fmaxf(fmaf(a[mt][0], sc0, sh0), 0.f);
                    a[mt][1] = fmaxf(fmaf(a[mt][1], sc0, sh0), 0.f);
                    a[mt][2] = fmaxf(fmaf(a[mt][2], sc4, sh4), 0.f);
                    a[mt][3] = fmaxf(fmaf(a[mt][3], sc4, sh4), 0.f);
                }
                a[mt][0] = to_tf32(a[mt][0]); a[mt][1] = to_tf32(a[mt][1]);
                a[mt][2] = to_tf32(a[mt][2]); a[mt][3] = to_tf32(a[mt][3]);
            }
#pragma unroll
            for (int nt = 0; nt < 8; nt++) {
                float b0 = Bs[buf][(kk + c) * PADN + ncol0 + nt * 8 + g];
                float b1 = Bs[buf][(kk + c + 4) * PADN + ncol0 + nt * 8 + g];
                b0 = to_tf32(b0); b1 = to_tf32(b1);
#pragma unroll
                for (int mt = 0; mt < 4; mt++) {
                    asm volatile(
                        "mma.sync.aligned.m16n8k8.row.col.f32.tf32.tf32.f32 "
                        "{%0,%1,%2,%3}, {%4,%5,%6,%7}, {%8,%9}, {%0,%1,%2,%3};"
                        : "+f"(acc[mt][nt][0]), "+f"(acc[mt][nt][1]),
                          "+f"(acc[mt][nt][2]), "+f"(acc[mt][nt][3])
                        : "r"(__float_as_uint(a[mt][0])), "r"(__float_as_uint(a[mt][1])),
                          "r"(__float_as_uint(a[mt][2])), "r"(__float_as_uint(a[mt][3])),
                          "r"(__float_as_uint(b0)), "r"(__float_as_uint(b1)));
                }
            }
        }
        __syncthreads();
    }

    // ---- epilogue ----
#pragma unroll
    for (int mt = 0; mt < 4; mt++) {
        int r0 = rowBase + mrow0 + mt * 16 + g;
        int r1 = r0 + 8;
        float m0 = 1.f, m1 = 1.f;
        if (MASKM) {
            m0 = MASK_AT(mask, r0) ? 1.f : 0.f;
            m1 = MASK_AT(mask, r1) ? 1.f : 0.f;
        }
        float* o0 = Out + (size_t)r0 * NDIM + nBase;
        float* o1 = Out + (size_t)r1 * NDIM + nBase;
#pragma unroll
        for (int nt = 0; nt < 8; nt++) {
            int col = ncol0 + nt * 8 + 2 * c;
            float bx = sBias[col], by = sBias[col + 1];
            float2 u, v;
            u.x = (acc[mt][nt][0] + bx) * m0;
            u.y = (acc[mt][nt][1] + by) * m0;
            v.x = (acc[mt][nt][2] + bx) * m1;
            v.y = (acc[mt][nt][3] + by) * m1;
            *(float2*)(o0 + col) = u;
            *(float2*)(o1 + col) = v;
        }
    }
}

// ---------------- pooled max over N ----------------
__global__ void poolmax_kernel() {
    int b = blockIdx.x, c = threadIdx.x;  // 256
    float mx = -3.4e38f;
    const float* p = g_h + ((size_t)b * NN) * C2 + c;
    for (int n = 0; n < NN; n++) mx = fmaxf(mx, p[(size_t)n * C2]);
    g_pool[b * C2 + c] = mx;
}

// ---------------- pbias = pooled @ W3[256:512] + b3 ----------------
__global__ void pbias_kernel(const float* __restrict__ W3, const float* __restrict__ b3) {
    __shared__ float sp[C2];
    int b = blockIdx.x, c = threadIdx.x;  // 256
    sp[c] = g_pool[b * C2 + c];
    __syncthreads();
    float v = b3[c];
    for (int k = 0; k < C2; k++) v = fmaf(sp[k], W3[(size_t)(C2 + k) * C2 + c], v);
    g_pbias[b * C2 + c] = v;
}

// ---------------- masked BN2 stats ----------------
__global__ __launch_bounds__(256) void stats2_kernel(const int* __restrict__ mask) {
    int c = threadIdx.x;
    int row0 = blockIdx.x * 32;
    float s = 0.f, ss = 0.f;
    for (int r = 0; r < 32; r++) {
        int row = row0 + r;
        if (MASK_AT(mask, row)) {
            float v = g_h2[(size_t)row * C2 + c];
            s += v; ss += v * v;
        }
    }
    atomicAdd(&g_stat[256 + c], s);
    atomicAdd(&g_stat[512 + c], ss);
}

// ---------------- final max ----------------
__global__ void finalmax_kernel(float* __restrict__ out) {
    int b = blockIdx.x, c = threadIdx.x;  // 128
    float mx = -3.4e38f;
    const float* p = g_h1 + ((size_t)b * NN) * ENC + c;
    for (int n = 0; n < NN; n++) mx = fmaxf(mx, p[(size_t)n * ENC]);
    out[b * ENC + c] = mx;
}

// ---------------- launch ----------------
extern "C" void kernel_launch(void* const* d_in, const int* in_sizes, int n_in,
                              void* d_out, int out_size) {
    const float* x  = (const float*)d_in[0];
    const int*   mk = (const int*)d_in[1];
    const float* W1 = (const float*)d_in[2];
    const float* b1 = (const float*)d_in[3];
    const float* g1 = (const float*)d_in[4];
    const float* be1= (const float*)d_in[5];
    const float* W2 = (const float*)d_in[6];
    const float* b2 = (const float*)d_in[7];
    const float* W3 = (const float*)d_in[8];
    const float* b3 = (const float*)d_in[9];
    const float* g2 = (const float*)d_in[10];
    const float* be2= (const float*)d_in[11];
    const float* W4 = (const float*)d_in[12];
    const float* b4 = (const float*)d_in[13];
    float* out = (float*)d_out;

    zero_stats_kernel<<<1, 256>>>();
    k1_kernel<<<MTOT / 32, 128>>>(x, mk, W1, b1);
    fin1_kernel<<<1, 128>>>(g1, be1);

    mma_gemm<128, 256, 2><<<dim3(MTOT / 128, 2), 128>>>(W2, b2, mk);
    poolmax_kernel<<<BB, 256>>>();
    pbias_kernel<<<BB, 256>>>(W3, b3);
    mma_gemm<256, 256, 3><<<dim3(MTOT / 128, 2), 128>>>(W3, nullptr, mk);
    stats2_kernel<<<MTOT / 32, 256>>>(mk);
    fin2_kernel<<<1, 256>>>(g2, be2);
    mma_gemm<256, 128, 4><<<dim3(MTOT / 128, 1), 128>>>(W4, b4, mk);
    finalmax_kernel<<<BB, 128>>>(out);
}